// round 8
// baseline (speedup 1.0000x reference)
#include <cuda_runtime.h>
#include <cstdint>

#define DM   128
#define SL   2048
#define NB   32
#define WIN  64
#define WROW 132                 // padded band row: [0]=0, [1..127]=w, [128..131]=0
#define NTILE 32                 // l-tiles per sequence (64 l each) for proj partial sums
#define TI   32                  // i-tile of band kernel
#define WR   (TI + 2*WIN - 2)    // 158 j-window rows
#define WRP  161                 // pre-shifted w row width (odd -> conflict-free)
#define DH   64                  // d-half per aft CTA
#define AFT_SMEM ((2*WR*DH + TI*WRP)*4)          // 101504 B -> 2 CTAs/SM
#define PROJ_SMEM (DM*64*8 + 64*DM*4)            // x-dup 64K + e_sh 32K = 98304 B

typedef unsigned long long u64;

// ---------- scratch (device globals: allocation-free) ----------
__device__ float g_q[(size_t)NB*SL*DM];   // q, then y after k_aft
__device__ float g_k[(size_t)NB*SL*DM];   // e = exp(k)
__device__ float g_v[(size_t)NB*SL*DM];   // u = e*v
__device__ float g_w[(size_t)SL*WROW];    // exp(pb)-1, padded band rows
__device__ float g_pse[NB*NTILE*DM];
__device__ float g_psu[NB*NTILE*DM];
__device__ float g_Se[NB*DM];
__device__ float g_Su[NB*DM];

// ---------- packed f32x2 helpers ----------
__device__ __forceinline__ u64 pack_dup(float x){
  u64 r; unsigned xi = __float_as_uint(x);
  asm("mov.b64 %0, {%1,%2};" : "=l"(r) : "r"(xi), "r"(xi));
  return r;
}
__device__ __forceinline__ u64 pack2(float x, float y){
  u64 r;
  asm("mov.b64 %0, {%1,%2};" : "=l"(r) : "r"(__float_as_uint(x)), "r"(__float_as_uint(y)));
  return r;
}
__device__ __forceinline__ float2 unpack2(u64 v){
  unsigned lo, hi;
  asm("mov.b64 {%0,%1}, %2;" : "=r"(lo), "=r"(hi) : "l"(v));
  return make_float2(__uint_as_float(lo), __uint_as_float(hi));
}
__device__ __forceinline__ void fma2(u64 &d, u64 a, u64 b){
  asm("fma.rn.f32x2 %0, %1, %2, %0;" : "+l"(d) : "l"(a), "l"(b));
}
__device__ __forceinline__ u64 add2(u64 a, u64 b){
  u64 r; asm("add.rn.f32x2 %0, %1, %2;" : "=l"(r) : "l"(a), "l"(b)); return r;
}
__device__ __forceinline__ u64 mul2(u64 a, u64 b){
  u64 r; asm("mul.rn.f32x2 %0, %1, %2;" : "=l"(r) : "l"(a), "l"(b)); return r;
}

// d-pair GEMM over one x-tile: acc[li][dp] += dup(x[c][li]) * Wpair(c, d0+2dp)
__device__ __forceinline__ void gemm_tile(const u64* __restrict__ xr,
                                          const float* __restrict__ W, int d0,
                                          u64 acc[4][4])
{
  #pragma unroll
  for (int a = 0; a < 4; a++){
    #pragma unroll
    for (int b = 0; b < 4; b++) acc[a][b] = 0ULL;
  }
  const float* Wp = W + d0;
  #pragma unroll 4
  for (int c = 0; c < DM; c++){
    ulonglong2 w01 = *(const ulonglong2*)(Wp + (size_t)c*DM);
    ulonglong2 w23 = *(const ulonglong2*)(Wp + (size_t)c*DM + 4);
    ulonglong2 xa  = *(const ulonglong2*)(xr + c*64);
    ulonglong2 xb  = *(const ulonglong2*)(xr + c*64 + 2);
    fma2(acc[0][0], xa.x, w01.x); fma2(acc[0][1], xa.x, w01.y); fma2(acc[0][2], xa.x, w23.x); fma2(acc[0][3], xa.x, w23.y);
    fma2(acc[1][0], xa.y, w01.x); fma2(acc[1][1], xa.y, w01.y); fma2(acc[1][2], xa.y, w23.x); fma2(acc[1][3], xa.y, w23.y);
    fma2(acc[2][0], xb.x, w01.x); fma2(acc[2][1], xb.x, w01.y); fma2(acc[2][2], xb.x, w23.x); fma2(acc[2][3], xb.x, w23.y);
    fma2(acc[3][0], xb.y, w01.x); fma2(acc[3][1], xb.y, w01.y); fma2(acc[3][2], xb.y, w23.x); fma2(acc[3][3], xb.y, w23.y);
  }
}

// ---------------------------------------------------------------------------
// K1: fused QKV projection + e=exp(k), u=e*v, per-tile column sums of e and u.
// Block (lt, n), 256 thr. Thread: dg=tid&15 (8 d = 4 d-pairs), lg=tid>>4 (4 li).
// Dyn smem: x tile duplicated as u64 [128 c][64 li] (64K) + e_sh [64 li][128 d] (32K).
// No max-subtraction: num/den ratio is invariant to it; exp(k) <= e^6 is safe.
// ---------------------------------------------------------------------------
__global__ void __launch_bounds__(256, 2) k_proj3(
    const float* __restrict__ x,
    const float* __restrict__ Wq, const float* __restrict__ bq,
    const float* __restrict__ Wk, const float* __restrict__ bk,
    const float* __restrict__ Wv, const float* __restrict__ bv)
{
  extern __shared__ char dsm_raw[];
  u64*   xd   = (u64*)dsm_raw;                 // [128][64] dup'd x
  float* e_sh = (float*)(dsm_raw + DM*64*8);   // [64][128]
  const int lt = blockIdx.x, n = blockIdx.y;
  const int l0 = lt*64, tid = threadIdx.x;

  // load x tile dup'd: x[n][c][l0+li]
  const float* xb = x + ((size_t)n*DM)*SL + l0;
  #pragma unroll
  for (int itr = 0; itr < 8; itr++){
    int idx = itr*256 + tid;                   // 0..2047
    int c = idx >> 4, l4 = (idx & 15)*4;
    float4 v4 = *(const float4*)(xb + (size_t)c*SL + l4);
    ulonglong2 da; da.x = pack_dup(v4.x); da.y = pack_dup(v4.y);
    ulonglong2 db; db.x = pack_dup(v4.z); db.y = pack_dup(v4.w);
    *(ulonglong2*)(xd + c*64 + l4)     = da;
    *(ulonglong2*)(xd + c*64 + l4 + 2) = db;
  }
  __syncthreads();

  const int dg = tid & 15, lg = tid >> 4;
  const int d0 = dg*8, li0 = lg*4;
  const u64* xr = xd + li0;
  u64 acc[4][4];

  // ---- q ----
  gemm_tile(xr, Wq, d0, acc);
  {
    ulonglong2 b01 = *(const ulonglong2*)(bq + d0);
    ulonglong2 b23 = *(const ulonglong2*)(bq + d0 + 4);
    float* op = g_q + (((size_t)n*SL + l0 + li0)*DM + d0);
    #pragma unroll
    for (int li = 0; li < 4; li++){
      ulonglong2 A, B;
      A.x = add2(acc[li][0], b01.x); A.y = add2(acc[li][1], b01.y);
      B.x = add2(acc[li][2], b23.x); B.y = add2(acc[li][3], b23.y);
      *(ulonglong2*)(op + (size_t)li*DM)     = A;
      *(ulonglong2*)(op + (size_t)li*DM + 4) = B;
    }
  }

  // ---- k -> e = exp(k) ----
  u64 se_acc[4] = {0,0,0,0};
  gemm_tile(xr, Wk, d0, acc);
  {
    ulonglong2 b01 = *(const ulonglong2*)(bk + d0);
    ulonglong2 b23 = *(const ulonglong2*)(bk + d0 + 4);
    u64 bb[4] = { b01.x, b01.y, b23.x, b23.y };
    float* op = g_k + (((size_t)n*SL + l0 + li0)*DM + d0);
    #pragma unroll
    for (int li = 0; li < 4; li++){
      u64 ep[4];
      #pragma unroll
      for (int dp = 0; dp < 4; dp++){
        float2 t = unpack2(add2(acc[li][dp], bb[dp]));
        ep[dp] = pack2(__expf(t.x), __expf(t.y));
        se_acc[dp] = add2(se_acc[dp], ep[dp]);
      }
      ulonglong2 A; A.x = ep[0]; A.y = ep[1];
      ulonglong2 B; B.x = ep[2]; B.y = ep[3];
      *(ulonglong2*)(op + (size_t)li*DM)     = A;
      *(ulonglong2*)(op + (size_t)li*DM + 4) = B;
      *(ulonglong2*)(e_sh + (li0+li)*DM + d0)     = A;
      *(ulonglong2*)(e_sh + (li0+li)*DM + d0 + 4) = B;
    }
  }

  // ---- v -> u = e*v ----
  u64 su_acc[4] = {0,0,0,0};
  gemm_tile(xr, Wv, d0, acc);
  {
    ulonglong2 b01 = *(const ulonglong2*)(bv + d0);
    ulonglong2 b23 = *(const ulonglong2*)(bv + d0 + 4);
    u64 bb[4] = { b01.x, b01.y, b23.x, b23.y };
    float* op = g_v + (((size_t)n*SL + l0 + li0)*DM + d0);
    #pragma unroll
    for (int li = 0; li < 4; li++){
      ulonglong2 Ea = *(const ulonglong2*)(e_sh + (li0+li)*DM + d0);
      ulonglong2 Eb = *(const ulonglong2*)(e_sh + (li0+li)*DM + d0 + 4);
      u64 ev[4] = { Ea.x, Ea.y, Eb.x, Eb.y };
      u64 up[4];
      #pragma unroll
      for (int dp = 0; dp < 4; dp++){
        u64 vv = add2(acc[li][dp], bb[dp]);
        up[dp] = mul2(ev[dp], vv);
        su_acc[dp] = add2(su_acc[dp], up[dp]);
      }
      ulonglong2 A; A.x = up[0]; A.y = up[1];
      ulonglong2 B; B.x = up[2]; B.y = up[3];
      *(ulonglong2*)(op + (size_t)li*DM)     = A;
      *(ulonglong2*)(op + (size_t)li*DM + 4) = B;
    }
  }

  // ---- partial column sums -> g_pse/g_psu (reduce over 16 lg groups) ----
  __syncthreads();                 // all e_sh reads done; reuse as scratch
  u64* red = (u64*)e_sh;           // [16 lg][64 u64] for se, +1024 for su
  #pragma unroll
  for (int dp = 0; dp < 4; dp++){
    red[lg*64 + dg*4 + dp]        = se_acc[dp];
    red[1024 + lg*64 + dg*4 + dp] = su_acc[dp];
  }
  __syncthreads();
  if (tid < 64){
    u64 s = 0, t = 0;
    #pragma unroll
    for (int g = 0; g < 16; g++){
      s = add2(s, red[g*64 + tid]);
      t = add2(t, red[1024 + g*64 + tid]);
    }
    const size_t base = ((size_t)(n*NTILE + lt))*DM;
    ((u64*)(g_pse + base))[tid] = s;
    ((u64*)(g_psu + base))[tid] = t;
  }
}

// ---------------------------------------------------------------------------
// K2: reduce tile partials to Se, Su.
// ---------------------------------------------------------------------------
__global__ void __launch_bounds__(128) k_sum2()
{
  const int n = blockIdx.x, d = threadIdx.x;
  float se = 0.f, su = 0.f;
  #pragma unroll
  for (int t = 0; t < NTILE; t++){
    se += g_pse[((size_t)(n*NTILE + t))*DM + d];
    su += g_psu[((size_t)(n*NTILE + t))*DM + d];
  }
  g_Se[n*DM + d] = se;
  g_Su[n*DM + d] = su;
}

// ---------------------------------------------------------------------------
// K3: band weights, no max pass:  w[i][1+t] = exp(pb[i,j]) - 1 in band, 0 outside.
// ---------------------------------------------------------------------------
__global__ void __launch_bounds__(128) k_pb(const float* __restrict__ pbias)
{
  const int i = blockIdx.x;
  for (int tw = threadIdx.x; tw < WROW; tw += 128){
    float val = 0.f;
    if (tw >= 1 && tw <= 127){
      int j = i - WIN + tw;            // j = i - 63 + (tw-1)
      if (j >= 0 && j < SL) val = __expf(pbias[(size_t)i*SL + j]) - 1.f;
    }
    g_w[(size_t)i*WROW + tw] = val;
  }
}

// ---------------------------------------------------------------------------
// K4: banded AFT core + sigmoid gate, d-split (2 CTAs of 64 d) -> 2 CTAs/SM.
//   num[i,d] = Su[d] + sum_jj w_sh[i_local][jj] * u_sh[jj][d]   (den with e, Se)
// Thread: dg=tid&7 (8 d = 4 pairs), ig=tid>>3 (1 i). Pre-shifted w: no clamps.
// ---------------------------------------------------------------------------
__global__ void __launch_bounds__(256, 2) k_aft()
{
  extern __shared__ float dsm[];
  float* u_sh = dsm;                  // [WR][64]
  float* e_sh = dsm + WR*DH;          // [WR][64]
  float* w_sh = dsm + 2*WR*DH;        // [TI][WRP]
  const int it = blockIdx.x, n = blockIdx.y, dh = blockIdx.z;
  const int i0 = it*TI, j0 = i0 - (WIN-1);
  const int tid = threadIdx.x;

  const float* ug = g_v + ((size_t)n*SL)*DM + dh*DH;
  const float* eg = g_k + ((size_t)n*SL)*DM + dh*DH;
  for (int idx = tid; idx < WR*16; idx += 256){
    int row = idx >> 4, c4 = (idx & 15)*4;
    int j = j0 + row;
    float4 vu, ve;
    if (j >= 0 && j < SL){
      vu = *(const float4*)(ug + (size_t)j*DM + c4);
      ve = *(const float4*)(eg + (size_t)j*DM + c4);
    } else {
      vu = make_float4(0.f,0.f,0.f,0.f); ve = vu;
    }
    *(float4*)&u_sh[row*DH + c4] = vu;
    *(float4*)&e_sh[row*DH + c4] = ve;
  }
  // pre-shifted w rows: w_sh[il][jj] = band weight for (i0+il, j0+jj)
  #pragma unroll 4
  for (int il = 0; il < TI; il++){
    if (tid < WRP){
      int tw = tid - il + 1;
      float val = (tw >= 0 && tw < WROW) ? g_w[(size_t)(i0+il)*WROW + tw] : 0.f;
      w_sh[il*WRP + tid] = val;
    }
  }
  __syncthreads();

  const int dg = tid & 7, ig = tid >> 3;
  const int d0 = dg*8;
  const float* Sup = g_Su + n*DM + dh*DH + d0;
  const float* Sep = g_Se + n*DM + dh*DH + d0;
  ulonglong2 s01 = *(const ulonglong2*)Sup;
  ulonglong2 s23 = *(const ulonglong2*)(Sup + 4);
  ulonglong2 z01 = *(const ulonglong2*)Sep;
  ulonglong2 z23 = *(const ulonglong2*)(Sep + 4);
  u64 an0 = s01.x, an1 = s01.y, an2 = s23.x, an3 = s23.y;
  u64 ad0 = z01.x, ad1 = z01.y, ad2 = z23.x, ad3 = z23.y;

  const float* wr = w_sh + ig*WRP;
  #pragma unroll 2
  for (int jj = 0; jj < WR; jj++){
    const float* ub = u_sh + jj*DH + d0;
    const float* eb = e_sh + jj*DH + d0;
    ulonglong2 ua = *(const ulonglong2*)ub;
    ulonglong2 uc = *(const ulonglong2*)(ub + 4);
    ulonglong2 ea = *(const ulonglong2*)eb;
    ulonglong2 ec = *(const ulonglong2*)(eb + 4);
    u64 wd = pack_dup(wr[jj]);
    fma2(an0, ua.x, wd); fma2(an1, ua.y, wd); fma2(an2, uc.x, wd); fma2(an3, uc.y, wd);
    fma2(ad0, ea.x, wd); fma2(ad1, ea.y, wd); fma2(ad2, ec.x, wd); fma2(ad3, ec.y, wd);
  }

  // y = sigmoid(q) * num/den, in place over g_q (this CTA owns (i, dh) slice)
  float* qp = g_q + (((size_t)n*SL + i0 + ig))*DM + dh*DH + d0;
  float4 qa = *(const float4*)qp;
  float4 qb = *(const float4*)(qp + 4);
  float2 N0 = unpack2(an0), N1 = unpack2(an1), N2 = unpack2(an2), N3 = unpack2(an3);
  float2 D0 = unpack2(ad0), D1 = unpack2(ad1), D2 = unpack2(ad2), D3 = unpack2(ad3);
  float4 ya, yb;
  ya.x = __fdividef(1.f, 1.f + __expf(-qa.x)) * __fdividef(N0.x, D0.x);
  ya.y = __fdividef(1.f, 1.f + __expf(-qa.y)) * __fdividef(N0.y, D0.y);
  ya.z = __fdividef(1.f, 1.f + __expf(-qa.z)) * __fdividef(N1.x, D1.x);
  ya.w = __fdividef(1.f, 1.f + __expf(-qa.w)) * __fdividef(N1.y, D1.y);
  yb.x = __fdividef(1.f, 1.f + __expf(-qb.x)) * __fdividef(N2.x, D2.x);
  yb.y = __fdividef(1.f, 1.f + __expf(-qb.y)) * __fdividef(N2.y, D2.y);
  yb.z = __fdividef(1.f, 1.f + __expf(-qb.z)) * __fdividef(N3.x, D3.x);
  yb.w = __fdividef(1.f, 1.f + __expf(-qb.w)) * __fdividef(N3.y, D3.y);
  *(float4*)qp       = ya;
  *(float4*)(qp + 4) = yb;
}

// ---------------------------------------------------------------------------
// K5: output projection + transpose to [n][c][l]  (unchanged from passing kernel)
// ---------------------------------------------------------------------------
__global__ void __launch_bounds__(256, 2) k_oproj(
    const float* __restrict__ Wo, const float* __restrict__ bo,
    float* __restrict__ out)
{
  __shared__ float sh[DM*68];
  const int lt = blockIdx.x, n = blockIdx.y, l0 = lt*64, tid = threadIdx.x;

  {
    const int lp = tid & 31;
    const int cg = tid >> 5;
    const float* yb = g_q + ((size_t)n*SL + l0)*DM;
    #pragma unroll
    for (int pass = 0; pass < 4; pass++){
      int c4 = cg + pass*8;
      const float* ya = yb + (size_t)(2*lp)*DM + c4*4;
      float4 a = *(const float4*)ya;
      float4 b = *(const float4*)(ya + DM);
      *(float2*)&sh[(c4*4+0)*68 + 2*lp] = make_float2(a.x, b.x);
      *(float2*)&sh[(c4*4+1)*68 + 2*lp] = make_float2(a.y, b.y);
      *(float2*)&sh[(c4*4+2)*68 + 2*lp] = make_float2(a.z, b.z);
      *(float2*)&sh[(c4*4+3)*68 + 2*lp] = make_float2(a.w, b.w);
    }
  }
  __syncthreads();

  const int dg = tid & 31, lg = tid >> 5;
  const int d0 = dg*4, li0 = lg*8;
  u64 acc[4][4];
  #pragma unroll
  for (int a1=0;a1<4;a1++){
    #pragma unroll
    for (int b1=0;b1<4;b1++) acc[a1][b1] = 0ULL;
  }

  const float* Wp  = Wo + d0;
  const float* shx = sh + li0;
  #pragma unroll 4
  for (int c = 0; c < DM; c++){
    float4 w4 = *(const float4*)(Wp + (size_t)c*DM);
    u64 wd0 = pack_dup(w4.x), wd1 = pack_dup(w4.y), wd2 = pack_dup(w4.z), wd3 = pack_dup(w4.w);
    const u64* xp = (const u64*)(shx + c*68);
    u64 x0 = xp[0], x1 = xp[1], x2 = xp[2], x3 = xp[3];
    fma2(acc[0][0], x0, wd0); fma2(acc[0][1], x0, wd1); fma2(acc[0][2], x0, wd2); fma2(acc[0][3], x0, wd3);
    fma2(acc[1][0], x1, wd0); fma2(acc[1][1], x1, wd1); fma2(acc[1][2], x1, wd2); fma2(acc[1][3], x1, wd3);
    fma2(acc[2][0], x2, wd0); fma2(acc[2][1], x2, wd1); fma2(acc[2][2], x2, wd2); fma2(acc[2][3], x2, wd3);
    fma2(acc[3][0], x3, wd0); fma2(acc[3][1], x3, wd1); fma2(acc[3][2], x3, wd2); fma2(acc[3][3], x3, wd3);
  }
  __syncthreads();

  float4 b4 = *(const float4*)(bo + d0);
  #pragma unroll
  for (int pr = 0; pr < 4; pr++){
    float2 r0 = unpack2(acc[pr][0]);
    float2 r1 = unpack2(acc[pr][1]);
    float2 r2 = unpack2(acc[pr][2]);
    float2 r3 = unpack2(acc[pr][3]);
    *(float2*)&sh[(d0+0)*68 + li0 + 2*pr] = make_float2(r0.x+b4.x, r0.y+b4.x);
    *(float2*)&sh[(d0+1)*68 + li0 + 2*pr] = make_float2(r1.x+b4.y, r1.y+b4.y);
    *(float2*)&sh[(d0+2)*68 + li0 + 2*pr] = make_float2(r2.x+b4.z, r2.y+b4.z);
    *(float2*)&sh[(d0+3)*68 + li0 + 2*pr] = make_float2(r3.x+b4.w, r3.y+b4.w);
  }
  __syncthreads();

  float* ob = out + ((size_t)n*DM)*SL + l0;
  #pragma unroll
  for (int itr = 0; itr < 8; itr++){
    int idx = itr*256 + tid;
    int d = idx >> 4, l4 = (idx & 15)*4;
    float4 v4 = *(const float4*)&sh[d*68 + l4];
    *(float4*)(ob + (size_t)d*SL + l4) = v4;
  }
}

// ---------------------------------------------------------------------------
extern "C" void kernel_launch(void* const* d_in, const int* in_sizes, int n_in,
                              void* d_out, int out_size)
{
  const float* x  = (const float*)d_in[0];
  const float* Wq = (const float*)d_in[1];
  const float* bq = (const float*)d_in[2];
  const float* Wk = (const float*)d_in[3];
  const float* bk = (const float*)d_in[4];
  const float* Wv = (const float*)d_in[5];
  const float* bv = (const float*)d_in[6];
  const float* Wo = (const float*)d_in[7];
  const float* bo = (const float*)d_in[8];
  const float* pb = (const float*)d_in[9];
  float* out = (float*)d_out;

  cudaFuncSetAttribute(k_proj3, cudaFuncAttributeMaxDynamicSharedMemorySize, PROJ_SMEM);
  cudaFuncSetAttribute(k_aft,   cudaFuncAttributeMaxDynamicSharedMemorySize, AFT_SMEM);

  k_proj3<<<dim3(SL/64, NB), 256, PROJ_SMEM>>>(x, Wq, bq, Wk, bk, Wv, bv);
  k_pb   <<<SL, 128>>>(pb);
  k_sum2 <<<NB, 128>>>();
  k_aft  <<<dim3(SL/TI, NB, 2), 256, AFT_SMEM>>>();
  k_oproj<<<dim3(SL/64, NB), 256>>>(Wo, bo, out);
}

// round 9
// speedup vs baseline: 1.5979x; 1.5979x over previous
#include <cuda_runtime.h>
#include <cstdint>

#define DM   128
#define SL   2048
#define NB   32
#define WIN  64
#define WROW 132                 // padded band row: [0]=0, [1..127]=w, [128..131]=0
#define NCH  16
#define CHL  (SL/NCH)            // 128
#define TI   128                 // i-tile of band kernel
#define WR   (TI + 2*WIN - 2)    // 254 j-window rows
#define DH   64                  // d-half per aft CTA
#define AFT_SMEM ((2*WR*DH + TI*WROW)*4)  // 197632 B -> 1 CTA/SM

typedef unsigned long long u64;

// ---------- scratch (device globals: allocation-free) ----------
__device__ float g_q[(size_t)NB*SL*DM];   // q, then y after k_aft
__device__ float g_k[(size_t)NB*SL*DM];   // k, then e = exp(k)
__device__ float g_v[(size_t)NB*SL*DM];   // v, then u = e*v
__device__ float g_w[(size_t)SL*WROW];    // exp(pb)-1 padded band rows
__device__ float g_pse[NB*NCH*DM];
__device__ float g_psu[NB*NCH*DM];
__device__ float g_Se[NB*DM];
__device__ float g_Su[NB*DM];

// ---------- packed f32x2 helpers (FFMA2) ----------
__device__ __forceinline__ u64 pack_dup(float x){
  u64 r; unsigned xi = __float_as_uint(x);
  asm("mov.b64 %0, {%1,%2};" : "=l"(r) : "r"(xi), "r"(xi));
  return r;
}
__device__ __forceinline__ float2 unpack2(u64 v){
  unsigned lo, hi;
  asm("mov.b64 {%0,%1}, %2;" : "=r"(lo), "=r"(hi) : "l"(v));
  return make_float2(__uint_as_float(lo), __uint_as_float(hi));
}
__device__ __forceinline__ void fma2(u64 &d, u64 a, u64 b){
  asm("fma.rn.f32x2 %0, %1, %2, %0;" : "+l"(d) : "l"(a), "l"(b));
}

// ---------------------------------------------------------------------------
// K1: QKV projection (proven R4 version).
// q/k/v[n,l,d] = sum_c x[n,c,l]*W[c,d] + b[d]
// ---------------------------------------------------------------------------
__global__ void __launch_bounds__(256, 2) k_proj(
    const float* __restrict__ x,
    const float* __restrict__ Wq, const float* __restrict__ bq,
    const float* __restrict__ Wk, const float* __restrict__ bk,
    const float* __restrict__ Wv, const float* __restrict__ bv)
{
  __shared__ float sh[DM*68];
  const int lt = blockIdx.x, n = blockIdx.y, p = blockIdx.z;
  const int l0 = lt*64;
  const float* W    = (p==0) ? Wq : (p==1 ? Wk : Wv);
  const float* bias = (p==0) ? bq : (p==1 ? bk : bv);
  float* out        = (p==0) ? g_q : (p==1 ? g_k : g_v);
  const int tid = threadIdx.x;

  const float* xb = x + ((size_t)n*DM)*SL + l0;
  #pragma unroll
  for (int itr = 0; itr < 8; itr++){
    int idx = itr*256 + tid;
    int c = idx >> 4, l4 = (idx & 15)*4;
    float4 v4 = *(const float4*)(xb + (size_t)c*SL + l4);
    *(float4*)&sh[c*68 + l4] = v4;
  }
  __syncthreads();

  const int dg = tid & 31, lg = tid >> 5;
  const int d0 = dg*4, li0 = lg*8;
  u64 acc[4][4];
  #pragma unroll
  for (int a1=0;a1<4;a1++){
    #pragma unroll
    for (int b1=0;b1<4;b1++) acc[a1][b1] = 0ULL;
  }

  const float* Wp  = W + d0;
  const float* shx = sh + li0;
  #pragma unroll 4
  for (int c = 0; c < DM; c++){
    float4 w4 = *(const float4*)(Wp + (size_t)c*DM);
    u64 wd0 = pack_dup(w4.x), wd1 = pack_dup(w4.y), wd2 = pack_dup(w4.z), wd3 = pack_dup(w4.w);
    const u64* xp = (const u64*)(shx + c*68);
    u64 x0 = xp[0], x1 = xp[1], x2 = xp[2], x3 = xp[3];
    fma2(acc[0][0], x0, wd0); fma2(acc[0][1], x0, wd1); fma2(acc[0][2], x0, wd2); fma2(acc[0][3], x0, wd3);
    fma2(acc[1][0], x1, wd0); fma2(acc[1][1], x1, wd1); fma2(acc[1][2], x1, wd2); fma2(acc[1][3], x1, wd3);
    fma2(acc[2][0], x2, wd0); fma2(acc[2][1], x2, wd1); fma2(acc[2][2], x2, wd2); fma2(acc[2][3], x2, wd3);
    fma2(acc[3][0], x3, wd0); fma2(acc[3][1], x3, wd1); fma2(acc[3][2], x3, wd2); fma2(acc[3][3], x3, wd3);
  }

  float4 b4 = *(const float4*)(bias + d0);
  float* op = out + (((size_t)n*SL + l0 + li0)*DM + d0);
  #pragma unroll
  for (int pr = 0; pr < 4; pr++){
    float2 r0 = unpack2(acc[pr][0]);
    float2 r1 = unpack2(acc[pr][1]);
    float2 r2 = unpack2(acc[pr][2]);
    float2 r3 = unpack2(acc[pr][3]);
    *(float4*)(op + (size_t)(2*pr  )*DM) = make_float4(r0.x+b4.x, r1.x+b4.y, r2.x+b4.z, r3.x+b4.w);
    *(float4*)(op + (size_t)(2*pr+1)*DM) = make_float4(r0.y+b4.x, r1.y+b4.y, r2.y+b4.z, r3.y+b4.w);
  }
}

// ---------------------------------------------------------------------------
// K2a/K2b: e = exp(k), u = e*v (in place, NO max — ratio-invariant), column sums
// ---------------------------------------------------------------------------
__global__ void __launch_bounds__(128) k_expsum()
{
  const int n = blockIdx.x, ch = blockIdx.y, d = threadIdx.x;
  const size_t base = ((size_t)n*SL + ch*CHL)*DM + d;
  float se = 0.f, su = 0.f;
  #pragma unroll 4
  for (int l = 0; l < CHL; l++){
    size_t o = base + (size_t)l*DM;
    float e = __expf(g_k[o]);
    float u = e * g_v[o];
    g_k[o] = e; g_v[o] = u;
    se += e; su += u;
  }
  g_pse[(n*NCH + ch)*DM + d] = se;
  g_psu[(n*NCH + ch)*DM + d] = su;
}
__global__ void __launch_bounds__(128) k_sum2()
{
  const int n = blockIdx.x, d = threadIdx.x;
  float se = 0.f, su = 0.f;
  #pragma unroll
  for (int ch = 0; ch < NCH; ch++){
    se += g_pse[(n*NCH + ch)*DM + d];
    su += g_psu[(n*NCH + ch)*DM + d];
  }
  g_Se[n*DM + d] = se;
  g_Su[n*DM + d] = su;
}

// ---------------------------------------------------------------------------
// K3: band weights, no max pass:  w[i][1+t] = exp(pb[i,j]) - 1 in band, 0 outside.
// ---------------------------------------------------------------------------
__global__ void __launch_bounds__(128) k_pb(const float* __restrict__ pbias)
{
  const int i = blockIdx.x;
  for (int tw = threadIdx.x; tw < WROW; tw += 128){
    float val = 0.f;
    if (tw >= 1 && tw <= 127){
      int j = i - WIN + tw;            // j = i - 63 + (tw-1)
      if (j >= 0 && j < SL) val = __expf(pbias[(size_t)i*SL + j]) - 1.f;
    }
    g_w[(size_t)i*WROW + tw] = val;
  }
}

// ---------------------------------------------------------------------------
// K4: banded AFT core + sigmoid gate.  Register-amortized: each thread owns
// 4 i x 8 d (32 FFMA2-accum pairs), so the 4 u/e LDS.128 per jj feed 32 FFMA2
// (ratio 4.0 vs 1.6 in the failed R8 version -> fma-bound, not LSU-bound).
// Block: TI=128 i x DH=64 d; 256 thr: dg=tid&7 (8 d), ig=tid>>3 (4 i each).
// ---------------------------------------------------------------------------
__global__ void __launch_bounds__(256, 1) k_aft()
{
  extern __shared__ float dsm[];
  float* u_sh = dsm;                  // [WR][64]
  float* e_sh = dsm + WR*DH;          // [WR][64]
  float* w_sh = dsm + 2*WR*DH;        // [TI][WROW]
  const int it = blockIdx.x, n = blockIdx.y, dh = blockIdx.z;
  const int i0 = it*TI, j0 = i0 - (WIN-1);
  const int tid = threadIdx.x;

  const float* ug = g_v + ((size_t)n*SL)*DM + dh*DH;
  const float* eg = g_k + ((size_t)n*SL)*DM + dh*DH;
  for (int idx = tid; idx < WR*16; idx += 256){
    int row = idx >> 4, c4 = (idx & 15)*4;
    int j = j0 + row;
    float4 vu, ve;
    if (j >= 0 && j < SL){
      vu = *(const float4*)(ug + (size_t)j*DM + c4);
      ve = *(const float4*)(eg + (size_t)j*DM + c4);
    } else {
      vu = make_float4(0.f,0.f,0.f,0.f); ve = vu;
    }
    *(float4*)&u_sh[row*DH + c4] = vu;
    *(float4*)&e_sh[row*DH + c4] = ve;
  }
  {
    const float4* wg = (const float4*)(g_w + (size_t)i0*WROW);
    float4* ws = (float4*)w_sh;
    for (int idx = tid; idx < TI*(WROW/4); idx += 256) ws[idx] = wg[idx];
  }
  __syncthreads();

  const int dg = tid & 7, ig = tid >> 3;     // ig 0..31
  const int d0 = dg*8, il0 = ig*4;

  const float* Sup = g_Su + n*DM + dh*DH + d0;
  const float* Sep = g_Se + n*DM + dh*DH + d0;
  ulonglong2 s01 = *(const ulonglong2*)Sup;
  ulonglong2 s23 = *(const ulonglong2*)(Sup + 4);
  ulonglong2 z01 = *(const ulonglong2*)Sep;
  ulonglong2 z23 = *(const ulonglong2*)(Sep + 4);

  u64 an[4][4], ad[4][4];
  #pragma unroll
  for (int r = 0; r < 4; r++){
    an[r][0] = s01.x; an[r][1] = s01.y; an[r][2] = s23.x; an[r][3] = s23.y;
    ad[r][0] = z01.x; ad[r][1] = z01.y; ad[r][2] = z23.x; ad[r][3] = z23.y;
  }

  const float* w0 = w_sh + il0*WROW;
  #pragma unroll 2
  for (int jj = 0; jj < WR; jj++){
    const float* ub = u_sh + jj*DH + d0;
    const float* eb = e_sh + jj*DH + d0;
    ulonglong2 ua = *(const ulonglong2*)ub;
    ulonglong2 uc = *(const ulonglong2*)(ub + 4);
    ulonglong2 ea = *(const ulonglong2*)eb;
    ulonglong2 ec = *(const ulonglong2*)(eb + 4);
    const int t0 = jj - il0 + 1;
    #pragma unroll
    for (int r = 0; r < 4; r++){
      int t = min(max(t0 - r, 0), 2*WIN);    // clamp into padded row -> 0 outside band
      u64 wd = pack_dup(w0[r*WROW + t]);
      fma2(an[r][0], ua.x, wd); fma2(an[r][1], ua.y, wd);
      fma2(an[r][2], uc.x, wd); fma2(an[r][3], uc.y, wd);
      fma2(ad[r][0], ea.x, wd); fma2(ad[r][1], ea.y, wd);
      fma2(ad[r][2], ec.x, wd); fma2(ad[r][3], ec.y, wd);
    }
  }

  // y = sigmoid(q) * num/den, in place over g_q (this CTA owns (i-tile, dh))
  #pragma unroll
  for (int r = 0; r < 4; r++){
    float* qp = g_q + ((size_t)n*SL + i0 + il0 + r)*DM + dh*DH + d0;
    float4 qa = *(const float4*)qp;
    float4 qb = *(const float4*)(qp + 4);
    float2 N0 = unpack2(an[r][0]), N1 = unpack2(an[r][1]);
    float2 N2 = unpack2(an[r][2]), N3 = unpack2(an[r][3]);
    float2 D0 = unpack2(ad[r][0]), D1 = unpack2(ad[r][1]);
    float2 D2 = unpack2(ad[r][2]), D3 = unpack2(ad[r][3]);
    float4 ya, yb;
    ya.x = __fdividef(1.f, 1.f + __expf(-qa.x)) * __fdividef(N0.x, D0.x);
    ya.y = __fdividef(1.f, 1.f + __expf(-qa.y)) * __fdividef(N0.y, D0.y);
    ya.z = __fdividef(1.f, 1.f + __expf(-qa.z)) * __fdividef(N1.x, D1.x);
    ya.w = __fdividef(1.f, 1.f + __expf(-qa.w)) * __fdividef(N1.y, D1.y);
    yb.x = __fdividef(1.f, 1.f + __expf(-qb.x)) * __fdividef(N2.x, D2.x);
    yb.y = __fdividef(1.f, 1.f + __expf(-qb.y)) * __fdividef(N2.y, D2.y);
    yb.z = __fdividef(1.f, 1.f + __expf(-qb.z)) * __fdividef(N3.x, D3.x);
    yb.w = __fdividef(1.f, 1.f + __expf(-qb.w)) * __fdividef(N3.y, D3.y);
    *(float4*)qp       = ya;
    *(float4*)(qp + 4) = yb;
  }
}

// ---------------------------------------------------------------------------
// K5: output projection + transpose to [n][c][l]  (proven R4 version)
// ---------------------------------------------------------------------------
__global__ void __launch_bounds__(256, 2) k_oproj(
    const float* __restrict__ Wo, const float* __restrict__ bo,
    float* __restrict__ out)
{
  __shared__ float sh[DM*68];
  const int lt = blockIdx.x, n = blockIdx.y, l0 = lt*64, tid = threadIdx.x;

  {
    const int lp = tid & 31;
    const int cg = tid >> 5;
    const float* yb = g_q + ((size_t)n*SL + l0)*DM;
    #pragma unroll
    for (int pass = 0; pass < 4; pass++){
      int c4 = cg + pass*8;
      const float* ya = yb + (size_t)(2*lp)*DM + c4*4;
      float4 a = *(const float4*)ya;
      float4 b = *(const float4*)(ya + DM);
      *(float2*)&sh[(c4*4+0)*68 + 2*lp] = make_float2(a.x, b.x);
      *(float2*)&sh[(c4*4+1)*68 + 2*lp] = make_float2(a.y, b.y);
      *(float2*)&sh[(c4*4+2)*68 + 2*lp] = make_float2(a.z, b.z);
      *(float2*)&sh[(c4*4+3)*68 + 2*lp] = make_float2(a.w, b.w);
    }
  }
  __syncthreads();

  const int dg = tid & 31, lg = tid >> 5;
  const int d0 = dg*4, li0 = lg*8;
  u64 acc[4][4];
  #pragma unroll
  for (int a1=0;a1<4;a1++){
    #pragma unroll
    for (int b1=0;b1<4;b1++) acc[a1][b1] = 0ULL;
  }

  const float* Wp  = Wo + d0;
  const float* shx = sh + li0;
  #pragma unroll 4
  for (int c = 0; c < DM; c++){
    float4 w4 = *(const float4*)(Wp + (size_t)c*DM);
    u64 wd0 = pack_dup(w4.x), wd1 = pack_dup(w4.y), wd2 = pack_dup(w4.z), wd3 = pack_dup(w4.w);
    const u64* xp = (const u64*)(shx + c*68);
    u64 x0 = xp[0], x1 = xp[1], x2 = xp[2], x3 = xp[3];
    fma2(acc[0][0], x0, wd0); fma2(acc[0][1], x0, wd1); fma2(acc[0][2], x0, wd2); fma2(acc[0][3], x0, wd3);
    fma2(acc[1][0], x1, wd0); fma2(acc[1][1], x1, wd1); fma2(acc[1][2], x1, wd2); fma2(acc[1][3], x1, wd3);
    fma2(acc[2][0], x2, wd0); fma2(acc[2][1], x2, wd1); fma2(acc[2][2], x2, wd2); fma2(acc[2][3], x2, wd3);
    fma2(acc[3][0], x3, wd0); fma2(acc[3][1], x3, wd1); fma2(acc[3][2], x3, wd2); fma2(acc[3][3], x3, wd3);
  }
  __syncthreads();

  float4 b4 = *(const float4*)(bo + d0);
  #pragma unroll
  for (int pr = 0; pr < 4; pr++){
    float2 r0 = unpack2(acc[pr][0]);
    float2 r1 = unpack2(acc[pr][1]);
    float2 r2 = unpack2(acc[pr][2]);
    float2 r3 = unpack2(acc[pr][3]);
    *(float2*)&sh[(d0+0)*68 + li0 + 2*pr] = make_float2(r0.x+b4.x, r0.y+b4.x);
    *(float2*)&sh[(d0+1)*68 + li0 + 2*pr] = make_float2(r1.x+b4.y, r1.y+b4.y);
    *(float2*)&sh[(d0+2)*68 + li0 + 2*pr] = make_float2(r2.x+b4.z, r2.y+b4.z);
    *(float2*)&sh[(d0+3)*68 + li0 + 2*pr] = make_float2(r3.x+b4.w, r3.y+b4.w);
  }
  __syncthreads();

  float* ob = out + ((size_t)n*DM)*SL + l0;
  #pragma unroll
  for (int itr = 0; itr < 8; itr++){
    int idx = itr*256 + tid;
    int d = idx >> 4, l4 = (idx & 15)*4;
    float4 v4 = *(const float4*)&sh[d*68 + l4];
    *(float4*)(ob + (size_t)d*SL + l4) = v4;
  }
}

// ---------------------------------------------------------------------------
extern "C" void kernel_launch(void* const* d_in, const int* in_sizes, int n_in,
                              void* d_out, int out_size)
{
  const float* x  = (const float*)d_in[0];
  const float* Wq = (const float*)d_in[1];
  const float* bq = (const float*)d_in[2];
  const float* Wk = (const float*)d_in[3];
  const float* bk = (const float*)d_in[4];
  const float* Wv = (const float*)d_in[5];
  const float* bv = (const float*)d_in[6];
  const float* Wo = (const float*)d_in[7];
  const float* bo = (const float*)d_in[8];
  const float* pb = (const float*)d_in[9];
  float* out = (float*)d_out;

  cudaFuncSetAttribute(k_aft, cudaFuncAttributeMaxDynamicSharedMemorySize, AFT_SMEM);

  k_proj  <<<dim3(SL/64, NB, 3), 256>>>(x, Wq, bq, Wk, bk, Wv, bv);
  k_pb    <<<SL, 128>>>(pb);
  k_expsum<<<dim3(NB, NCH), 128>>>();
  k_sum2  <<<NB, 128>>>();
  k_aft   <<<dim3(SL/TI, NB, 2), 256, AFT_SMEM>>>();
  k_oproj <<<dim3(SL/64, NB), 256>>>(Wo, bo, out);
}

// round 14
// speedup vs baseline: 5.1658x; 3.2328x over previous
#include <cuda_runtime.h>
#include <cuda_bf16.h>
#include <cstdint>

#define DM   128
#define SL   2048
#define NB   32
#define WIN  64
#define WROW 132
#define NTILE 16                 // 128-l tiles per sequence

// ---- proj smem ----
#define PPITCH 136               // bf16 elems per row (272B: stride%128==16 -> ldmatrix conflict-free)
#define PRJ_AH 0
#define PRJ_AL 34816
#define PRJ_BH 69632
#define PRJ_BL 104448
#define PRJ_RED 139264           // redE[4][128], redU[4][128] fp32
#define PRJ_BIAS (PRJ_RED + 4096)
#define PRJ_SMEM (PRJ_BIAS + 1536)   // 144896

// ---- aft smem (single bf16, 2 CTAs/SM) ----
#define ATI  64                  // i-tile
#define AKP  192                 // padded K (window 190)
#define APW  200                 // A pitch (400B: %128==16)
#define BPW  72                  // B pitch (144B: %128==16)
#define AFT_A 0                  // [64][200] bf16 = 25600
#define AFT_U 25600              // [192][72]      = 27648
#define AFT_E 53248
#define AFT_SS 80896             // su[64], se[64]
#define AFT_SMEM (AFT_SS + 512)  // 81408

// ---- oproj smem ----
#define OP_ST 69632              // stage fp32 [128][136] overlays B region
#define OP_BIAS 139264
#define OP_SMEM (OP_BIAS + 512)

// ---------- scratch ----------
__device__ float g_q[(size_t)NB*SL*DM];   // q, then y after aft
__device__ float g_k[(size_t)NB*SL*DM];   // e = exp(k)
__device__ float g_v[(size_t)NB*SL*DM];   // u = e*v
__device__ float g_w[(size_t)SL*WROW];    // exp(pb)-1 padded band rows
__device__ float g_pse[NB*NTILE*DM];
__device__ float g_psu[NB*NTILE*DM];
__device__ float g_Se[NB*DM];
__device__ float g_Su[NB*DM];
__device__ __nv_bfloat16 g_Wimg[4][2][DM*PPITCH];  // [mat q,k,v,o][hi/lo][c][d] pitch 136

// ---------- helpers ----------
__device__ __forceinline__ uint32_t smem_u32(const void* p){
  uint32_t a;
  asm("{ .reg .u64 t; cvta.to.shared.u64 t, %1; cvt.u32.u64 %0, t; }" : "=r"(a) : "l"(p));
  return a;
}
__device__ __forceinline__ void ldm4(uint32_t* r, uint32_t a){
  asm volatile("ldmatrix.sync.aligned.m8n8.x4.shared.b16 {%0,%1,%2,%3}, [%4];"
    : "=r"(r[0]),"=r"(r[1]),"=r"(r[2]),"=r"(r[3]) : "r"(a));
}
__device__ __forceinline__ void ldm4t(uint32_t* r, uint32_t a){
  asm volatile("ldmatrix.sync.aligned.m8n8.x4.trans.shared.b16 {%0,%1,%2,%3}, [%4];"
    : "=r"(r[0]),"=r"(r[1]),"=r"(r[2]),"=r"(r[3]) : "r"(a));
}
__device__ __forceinline__ void hmma(float* c, const uint32_t* a, uint32_t b0, uint32_t b1){
  asm volatile("mma.sync.aligned.m16n8k16.row.col.f32.bf16.bf16.f32 "
    "{%0,%1,%2,%3}, {%4,%5,%6,%7}, {%8,%9}, {%0,%1,%2,%3};"
    : "+f"(c[0]),"+f"(c[1]),"+f"(c[2]),"+f"(c[3])
    : "r"(a[0]),"r"(a[1]),"r"(a[2]),"r"(a[3]),"r"(b0),"r"(b1));
}
__device__ __forceinline__ float sigm(float x){
  return __fdividef(1.f, 1.f + __expf(-x));
}

// 128x128x128 GEMM, 2-term bf16 split (hh + hl + lh). Warp (wm in 0..3, wn in 0..1),
// warp tile 32(m) x 64(n). C[mf][nf][4] per PTX m16n8k16 layout.
__device__ __forceinline__ void gemm128_split(
    uint32_t AhU, uint32_t AlU, uint32_t BhU, uint32_t BlU,
    int wm, int wn, int lane, float C[2][8][4])
{
  #pragma unroll
  for (int mf=0;mf<2;mf++)
    #pragma unroll
    for (int nf=0;nf<8;nf++)
      #pragma unroll
      for (int k=0;k<4;k++) C[mf][nf][k] = 0.f;

  const uint32_t arow = wm*32 + (lane&15);
  const uint32_t kg = (lane>>4)*8;
  const uint32_t brow = lane&15;
  #pragma unroll
  for (int ks=0; ks<8; ks++){
    const uint32_t k0 = ks*16;
    uint32_t ah[2][4], al[2][4];
    #pragma unroll
    for (int mf=0;mf<2;mf++){
      uint32_t off = ((arow + mf*16)*PPITCH + k0 + kg)*2;
      ldm4(ah[mf], AhU + off);
      ldm4(al[mf], AlU + off);
    }
    uint32_t bh[8][2], bl[8][2];
    #pragma unroll
    for (int np=0;np<4;np++){
      uint32_t off = ((k0 + brow)*PPITCH + wn*64 + np*16 + kg)*2;
      uint32_t t[4];
      ldm4t(t, BhU + off);
      bh[np*2][0]=t[0]; bh[np*2][1]=t[1]; bh[np*2+1][0]=t[2]; bh[np*2+1][1]=t[3];
      ldm4t(t, BlU + off);
      bl[np*2][0]=t[0]; bl[np*2][1]=t[1]; bl[np*2+1][0]=t[2]; bl[np*2+1][1]=t[3];
    }
    #pragma unroll
    for (int mf=0;mf<2;mf++)
      #pragma unroll
      for (int nf=0;nf<8;nf++){
        hmma(C[mf][nf], ah[mf], bh[nf][0], bh[nf][1]);
        hmma(C[mf][nf], ah[mf], bl[nf][0], bl[nf][1]);
        hmma(C[mf][nf], al[mf], bh[nf][0], bh[nf][1]);
      }
  }
}

// ---------------------------------------------------------------------------
// K0: split W's into bf16 hi/lo images, [c][d] row-major pitch 136.
// ---------------------------------------------------------------------------
__global__ void __launch_bounds__(128) k_prepw(
    const float* __restrict__ Wq, const float* __restrict__ Wk,
    const float* __restrict__ Wv, const float* __restrict__ Wo)
{
  const int m = blockIdx.x, cs = blockIdx.y;
  const float* W = (m==0) ? Wq : (m==1) ? Wk : (m==2) ? Wv : Wo;
  const int d = threadIdx.x;
  for (int c = cs*16; c < cs*16 + 16; c++){
    float w = W[(size_t)c*DM + d];
    __nv_bfloat16 h = __float2bfloat16(w);
    __nv_bfloat16 l = __float2bfloat16(w - __bfloat162float(h));
    g_Wimg[m][0][c*PPITCH + d] = h;
    g_Wimg[m][1][c*PPITCH + d] = l;
  }
}

// ---------------------------------------------------------------------------
// K1: tensor-core QKV projection + fused e=exp(k), u=e*v, tile column sums.
// Grid (16, NB), 256 threads.  Order: k -> v -> q.
// ---------------------------------------------------------------------------
__global__ void __launch_bounds__(256, 1) k_proj_mma(
    const float* __restrict__ x,  const float* __restrict__ bq,
    const float* __restrict__ bk, const float* __restrict__ bv)
{
  extern __shared__ char smem[];
  const int lt = blockIdx.x, n = blockIdx.y, l0 = lt*128;
  const int tid = threadIdx.x, wid = tid>>5, lane = tid&31;
  const int wm = wid&3, wn = wid>>2;
  __nv_bfloat16* Ah = (__nv_bfloat16*)(smem + PRJ_AH);
  __nv_bfloat16* Al = (__nv_bfloat16*)(smem + PRJ_AL);
  __nv_bfloat16* Bh = (__nv_bfloat16*)(smem + PRJ_BH);
  __nv_bfloat16* Bl = (__nv_bfloat16*)(smem + PRJ_BL);
  float* redE  = (float*)(smem + PRJ_RED);       // [4][128]
  float* redU  = redE + 512;
  float* sbias = redU + 512;                     // [k|v|q][128]
  const uint32_t AhU = smem_u32(Ah), AlU = smem_u32(Al);
  const uint32_t BhU = smem_u32(Bh), BlU = smem_u32(Bl);

  if (tid < 128){
    sbias[tid] = bk[tid]; sbias[128+tid] = bv[tid]; sbias[256+tid] = bq[tid];
  }

  // A = x^T tile: [l][c] hi/lo
  const float* xb = x + ((size_t)n*DM)*SL + l0;
  for (int idx = tid; idx < 128*32; idx += 256){
    int c = idx >> 5, l4 = (idx & 31)*4;
    float4 v4 = *(const float4*)(xb + (size_t)c*SL + l4);
    float vv[4] = {v4.x, v4.y, v4.z, v4.w};
    #pragma unroll
    for (int j=0;j<4;j++){
      __nv_bfloat16 h = __float2bfloat16(vv[j]);
      __nv_bfloat16 l = __float2bfloat16(vv[j] - __bfloat162float(h));
      Ah[(l4+j)*PPITCH + c] = h;
      Al[(l4+j)*PPITCH + c] = l;
    }
  }

  const int erow = l0 + wm*32 + (lane>>2);   // + mf*16 (+8)
  const int ecl0 = wn*64 + (lane&3)*2;       // + nf*8
  float C[2][8][4];

  // ================= k =================
  {
    const float4* sh_ = (const float4*)g_Wimg[1][0];
    const float4* sl_ = (const float4*)g_Wimg[1][1];
    float4* dh_ = (float4*)Bh; float4* dl_ = (float4*)Bl;
    for (int i = tid; i < 2176; i += 256){ dh_[i] = sh_[i]; dl_[i] = sl_[i]; }
  }
  __syncthreads();
  gemm128_split(AhU, AlU, BhU, BlU, wm, wn, lane, C);
  {
    float sE[8][2];
    #pragma unroll
    for (int nf=0;nf<8;nf++){ sE[nf][0]=0.f; sE[nf][1]=0.f; }
    #pragma unroll
    for (int mf=0;mf<2;mf++)
      #pragma unroll
      for (int nf=0;nf<8;nf++){
        int col = ecl0 + nf*8;
        float b0 = sbias[col], b1 = sbias[col+1];
        float e0 = __expf(C[mf][nf][0]+b0);
        float e1 = __expf(C[mf][nf][1]+b1);
        float e2 = __expf(C[mf][nf][2]+b0);
        float e3 = __expf(C[mf][nf][3]+b1);
        int r = erow + mf*16;
        *(float2*)(g_k + ((size_t)n*SL + r    )*DM + col) = make_float2(e0,e1);
        *(float2*)(g_k + ((size_t)n*SL + r + 8)*DM + col) = make_float2(e2,e3);
        sE[nf][0] += e0+e2; sE[nf][1] += e1+e3;
      }
    #pragma unroll
    for (int nf=0;nf<8;nf++){
      float s0 = sE[nf][0], s1 = sE[nf][1];
      s0 += __shfl_down_sync(0xFFFFFFFFu, s0, 16);
      s0 += __shfl_down_sync(0xFFFFFFFFu, s0, 8);
      s0 += __shfl_down_sync(0xFFFFFFFFu, s0, 4);
      s1 += __shfl_down_sync(0xFFFFFFFFu, s1, 16);
      s1 += __shfl_down_sync(0xFFFFFFFFu, s1, 8);
      s1 += __shfl_down_sync(0xFFFFFFFFu, s1, 4);
      if (lane < 4){
        int col = wn*64 + nf*8 + lane*2;
        redE[wm*128 + col] = s0;
        redE[wm*128 + col + 1] = s1;
      }
    }
  }
  __syncthreads();

  // ================= v -> u = e*v =================
  {
    const float4* sh_ = (const float4*)g_Wimg[2][0];
    const float4* sl_ = (const float4*)g_Wimg[2][1];
    float4* dh_ = (float4*)Bh; float4* dl_ = (float4*)Bl;
    for (int i = tid; i < 2176; i += 256){ dh_[i] = sh_[i]; dl_[i] = sl_[i]; }
  }
  __syncthreads();
  gemm128_split(AhU, AlU, BhU, BlU, wm, wn, lane, C);
  {
    float sU[8][2];
    #pragma unroll
    for (int nf=0;nf<8;nf++){ sU[nf][0]=0.f; sU[nf][1]=0.f; }
    #pragma unroll
    for (int mf=0;mf<2;mf++)
      #pragma unroll
      for (int nf=0;nf<8;nf++){
        int col = ecl0 + nf*8;
        float b0 = sbias[128+col], b1 = sbias[128+col+1];
        int r = erow + mf*16;
        float2 e01 = *(const float2*)(g_k + ((size_t)n*SL + r    )*DM + col); // own earlier store
        float2 e23 = *(const float2*)(g_k + ((size_t)n*SL + r + 8)*DM + col);
        float u0 = e01.x * (C[mf][nf][0]+b0);
        float u1 = e01.y * (C[mf][nf][1]+b1);
        float u2 = e23.x * (C[mf][nf][2]+b0);
        float u3 = e23.y * (C[mf][nf][3]+b1);
        *(float2*)(g_v + ((size_t)n*SL + r    )*DM + col) = make_float2(u0,u1);
        *(float2*)(g_v + ((size_t)n*SL + r + 8)*DM + col) = make_float2(u2,u3);
        sU[nf][0] += u0+u2; sU[nf][1] += u1+u3;
      }
    #pragma unroll
    for (int nf=0;nf<8;nf++){
      float s0 = sU[nf][0], s1 = sU[nf][1];
      s0 += __shfl_down_sync(0xFFFFFFFFu, s0, 16);
      s0 += __shfl_down_sync(0xFFFFFFFFu, s0, 8);
      s0 += __shfl_down_sync(0xFFFFFFFFu, s0, 4);
      s1 += __shfl_down_sync(0xFFFFFFFFu, s1, 16);
      s1 += __shfl_down_sync(0xFFFFFFFFu, s1, 8);
      s1 += __shfl_down_sync(0xFFFFFFFFu, s1, 4);
      if (lane < 4){
        int col = wn*64 + nf*8 + lane*2;
        redU[wm*128 + col] = s0;
        redU[wm*128 + col + 1] = s1;
      }
    }
  }
  __syncthreads();

  // ================= q =================
  {
    const float4* sh_ = (const float4*)g_Wimg[0][0];
    const float4* sl_ = (const float4*)g_Wimg[0][1];
    float4* dh_ = (float4*)Bh; float4* dl_ = (float4*)Bl;
    for (int i = tid; i < 2176; i += 256){ dh_[i] = sh_[i]; dl_[i] = sl_[i]; }
  }
  __syncthreads();
  gemm128_split(AhU, AlU, BhU, BlU, wm, wn, lane, C);
  #pragma unroll
  for (int mf=0;mf<2;mf++)
    #pragma unroll
    for (int nf=0;nf<8;nf++){
      int col = ecl0 + nf*8;
      float b0 = sbias[256+col], b1 = sbias[256+col+1];
      int r = erow + mf*16;
      *(float2*)(g_q + ((size_t)n*SL + r    )*DM + col) = make_float2(C[mf][nf][0]+b0, C[mf][nf][1]+b1);
      *(float2*)(g_q + ((size_t)n*SL + r + 8)*DM + col) = make_float2(C[mf][nf][2]+b0, C[mf][nf][3]+b1);
    }
  __syncthreads();

  if (tid < 128){
    g_pse[((size_t)n*NTILE + lt)*DM + tid] = redE[tid]+redE[128+tid]+redE[256+tid]+redE[384+tid];
    g_psu[((size_t)n*NTILE + lt)*DM + tid] = redU[tid]+redU[128+tid]+redU[256+tid]+redU[384+tid];
  }
}

// ---------------------------------------------------------------------------
// K2: reduce tile partials to Se, Su
// ---------------------------------------------------------------------------
__global__ void __launch_bounds__(128) k_sum2()
{
  const int n = blockIdx.x, d = threadIdx.x;
  float se = 0.f, su = 0.f;
  #pragma unroll
  for (int t = 0; t < NTILE; t++){
    se += g_pse[((size_t)n*NTILE + t)*DM + d];
    su += g_psu[((size_t)n*NTILE + t)*DM + d];
  }
  g_Se[n*DM + d] = se;
  g_Su[n*DM + d] = su;
}

// ---------------------------------------------------------------------------
// K3: band weights (no max): w[i][1+t] = exp(pb[i,j]) - 1 inside band, 0 outside
// ---------------------------------------------------------------------------
__global__ void __launch_bounds__(128) k_pb(const float* __restrict__ pbias)
{
  const int i = blockIdx.x;
  for (int tw = threadIdx.x; tw < WROW; tw += 128){
    float val = 0.f;
    if (tw >= 1 && tw <= 127){
      int j = i - WIN + tw;
      if (j >= 0 && j < SL) val = __expf(pbias[(size_t)i*SL + j]) - 1.f;
    }
    g_w[(size_t)i*WROW + tw] = val;
  }
}

// ---------------------------------------------------------------------------
// K4: banded AFT core on tensor cores + sigmoid gate.
// Per (i-tile 64, n, dh half of d):  A = pre-shifted band w [64][192] bf16,
// B = u and e windows [192][64] bf16;  num = A@u + Su, den = A@e + Se.
// Single bf16 is sufficient: |w| ~ 0.02 so the band GEMM is a ~0.5% correction
// to the fp32-exact Su/Se -> final error ~1e-5.
// ---------------------------------------------------------------------------
__global__ void __launch_bounds__(256, 2) k_aft_mma()
{
  extern __shared__ char smem[];
  __nv_bfloat16* Aw = (__nv_bfloat16*)(smem + AFT_A);
  __nv_bfloat16* Bu = (__nv_bfloat16*)(smem + AFT_U);
  __nv_bfloat16* Be = (__nv_bfloat16*)(smem + AFT_E);
  float* ss = (float*)(smem + AFT_SS);   // su[64], se[64]
  const uint32_t AwU = smem_u32(Aw), BuU = smem_u32(Bu), BeU = smem_u32(Be);
  const int it = blockIdx.x, n = blockIdx.y, dh = blockIdx.z;
  const int i0 = it*ATI, j0 = i0 - (WIN-1);
  const int tid = threadIdx.x, wid = tid>>5, lane = tid&31;
  const int wm = wid&3, wn = wid>>2;

  if (tid < 64){
    ss[tid]    = g_Su[n*DM + dh*64 + tid];
    ss[64+tid] = g_Se[n*DM + dh*64 + tid];
  }

  // B fill: u/e window rows (190 valid + 2 zero pad)
  const float* ug = g_v + ((size_t)n*SL)*DM + dh*64;
  const float* eg = g_k + ((size_t)n*SL)*DM + dh*64;
  for (int idx = tid; idx < AKP*16; idx += 256){
    int row = idx>>4, c4 = (idx&15)*4;
    int j = j0 + row;
    float4 fu, fe;
    if (row < (ATI + 2*WIN - 2) && j >= 0 && j < SL){
      fu = *(const float4*)(ug + (size_t)j*DM + c4);
      fe = *(const float4*)(eg + (size_t)j*DM + c4);
    } else { fu = make_float4(0.f,0.f,0.f,0.f); fe = fu; }
    *(__nv_bfloat162*)&Bu[row*BPW + c4]     = __floats2bfloat162_rn(fu.x, fu.y);
    *(__nv_bfloat162*)&Bu[row*BPW + c4 + 2] = __floats2bfloat162_rn(fu.z, fu.w);
    *(__nv_bfloat162*)&Be[row*BPW + c4]     = __floats2bfloat162_rn(fe.x, fe.y);
    *(__nv_bfloat162*)&Be[row*BPW + c4 + 2] = __floats2bfloat162_rn(fe.z, fe.w);
  }

  // A fill: Aw[il][jj] = w(i0+il, j0+jj); band offset tw = jj - il + 1 in [1,127]
  for (int idx = tid; idx < ATI*(AKP/4); idx += 256){
    int il = idx / (AKP/4), q4 = (idx % (AKP/4))*4;
    const float* wr = g_w + (size_t)(i0+il)*WROW;
    #pragma unroll
    for (int j=0;j<4;j++){
      int jj = q4 + j;
      int tw = jj - il + 1;
      float w = (tw >= 1 && tw <= 127) ? wr[tw] : 0.f;
      Aw[il*APW + jj] = __float2bfloat16(w);
    }
  }
  __syncthreads();

  float Cn[4][4], Cd[4][4];
  #pragma unroll
  for (int nf=0;nf<4;nf++)
    #pragma unroll
    for (int k=0;k<4;k++){ Cn[nf][k]=0.f; Cd[nf][k]=0.f; }

  const uint32_t arow = wm*16 + (lane&15);
  const uint32_t kg = (lane>>4)*8;
  const uint32_t brow = lane&15;
  #pragma unroll
  for (int ks=0; ks<AKP/16; ks++){
    const uint32_t k0 = ks*16;
    uint32_t a[4];
    ldm4(a, AwU + (arow*APW + k0 + kg)*2);
    uint32_t bu[4][2], be[4][2];
    #pragma unroll
    for (int np=0;np<2;np++){
      uint32_t off = ((k0 + brow)*BPW + wn*32 + np*16 + kg)*2;
      uint32_t t[4];
      ldm4t(t, BuU + off);
      bu[np*2][0]=t[0]; bu[np*2][1]=t[1]; bu[np*2+1][0]=t[2]; bu[np*2+1][1]=t[3];
      ldm4t(t, BeU + off);
      be[np*2][0]=t[0]; be[np*2][1]=t[1]; be[np*2+1][0]=t[2]; be[np*2+1][1]=t[3];
    }
    #pragma unroll
    for (int nf=0;nf<4;nf++){
      hmma(Cn[nf], a, bu[nf][0], bu[nf][1]);
      hmma(Cd[nf], a, be[nf][0], be[nf][1]);
    }
  }

  // y = sigmoid(q) * (num+Su)/(den+Se), in place over g_q
  const int row = i0 + wm*16 + (lane>>2);
  #pragma unroll
  for (int nf=0;nf<4;nf++){
    int col = wn*32 + nf*8 + (lane&3)*2;
    float su0 = ss[col], su1 = ss[col+1];
    float se0 = ss[64+col], se1 = ss[64+col+1];
    float* qp = g_q + ((size_t)n*SL + row)*DM + dh*64 + col;
    float2 q01 = *(float2*)qp;
    float2 q23 = *(float2*)(qp + 8*DM);
    float y0 = sigm(q01.x) * __fdividef(Cn[nf][0]+su0, Cd[nf][0]+se0);
    float y1 = sigm(q01.y) * __fdividef(Cn[nf][1]+su1, Cd[nf][1]+se1);
    float y2 = sigm(q23.x) * __fdividef(Cn[nf][2]+su0, Cd[nf][2]+se0);
    float y3 = sigm(q23.y) * __fdividef(Cn[nf][3]+su1, Cd[nf][3]+se1);
    *(float2*)qp          = make_float2(y0, y1);
    *(float2*)(qp + 8*DM) = make_float2(y2, y3);
  }
}

// ---------------------------------------------------------------------------
// K5: tensor-core output projection + transpose to [n][c][l].
// ---------------------------------------------------------------------------
__global__ void __launch_bounds__(256, 1) k_oproj_mma(
    const float* __restrict__ bo, float* __restrict__ out)
{
  extern __shared__ char smem[];
  const int lt = blockIdx.x, n = blockIdx.y, l0 = lt*128;
  const int tid = threadIdx.x, wid = tid>>5, lane = tid&31;
  const int wm = wid&3, wn = wid>>2;
  __nv_bfloat16* Ah = (__nv_bfloat16*)(smem + PRJ_AH);
  __nv_bfloat16* Al = (__nv_bfloat16*)(smem + PRJ_AL);
  __nv_bfloat16* Bh = (__nv_bfloat16*)(smem + PRJ_BH);
  __nv_bfloat16* Bl = (__nv_bfloat16*)(smem + PRJ_BL);
  float* st  = (float*)(smem + OP_ST);          // overlays B after GEMM
  float* sbo = (float*)(smem + OP_BIAS);
  const uint32_t AhU = smem_u32(Ah), AlU = smem_u32(Al);
  const uint32_t BhU = smem_u32(Bh), BlU = smem_u32(Bl);

  if (tid < 128) sbo[tid] = bo[tid];

  // A = y tile [l][d] (row-major in g_q)
  const float* yb = g_q + ((size_t)n*SL + l0)*DM;
  for (int idx = tid; idx < 128*32; idx += 256){
    int r = idx >> 5, c4 = (idx & 31)*4;
    float4 v4 = *(const float4*)(yb + (size_t)r*DM + c4);
    float vv[4] = {v4.x, v4.y, v4.z, v4.w};
    #pragma unroll
    for (int j=0;j<4;j++){
      __nv_bfloat16 h = __float2bfloat16(vv[j]);
      __nv_bfloat16 l = __float2bfloat16(vv[j] - __bfloat162float(h));
      Ah[r*PPITCH + c4 + j] = h;
      Al[r*PPITCH + c4 + j] = l;
    }
  }
  {
    const float4* sh_ = (const float4*)g_Wimg[3][0];
    const float4* sl_ = (const float4*)g_Wimg[3][1];
    float4* dh_ = (float4*)Bh; float4* dl_ = (float4*)Bl;
    for (int i = tid; i < 2176; i += 256){ dh_[i] = sh_[i]; dl_[i] = sl_[i]; }
  }
  __syncthreads();

  float C[2][8][4];
  gemm128_split(AhU, AlU, BhU, BlU, wm, wn, lane, C);
  __syncthreads();   // done reading B -> reuse as stage

  #pragma unroll
  for (int mf=0;mf<2;mf++)
    #pragma unroll
    for (int nf=0;nf<8;nf++){
      int row = wm*32 + mf*16 + (lane>>2);
      int col = wn*64 + nf*8 + (lane&3)*2;
      float b0 = sbo[col], b1 = sbo[col+1];
      st[col*PPITCH + row]         = C[mf][nf][0] + b0;
      st[(col+1)*PPITCH + row]     = C[mf][nf][1] + b1;
      st[col*PPITCH + row + 8]     = C[mf][nf][2] + b0;
      st[(col+1)*PPITCH + row + 8] = C[mf][nf][3] + b1;
    }
  __syncthreads();

  for (int idx = tid; idx < 128*32; idx += 256){
    int d = idx >> 5, l4 = (idx & 31)*4;
    float4 v4 = *(const float4*)&st[d*PPITCH + l4];
    *(float4*)(out + ((size_t)n*DM + d)*SL + l0 + l4) = v4;
  }
}

// ---------------------------------------------------------------------------
extern "C" void kernel_launch(void* const* d_in, const int* in_sizes, int n_in,
                              void* d_out, int out_size)
{
  const float* x  = (const float*)d_in[0];
  const float* Wq = (const float*)d_in[1];
  const float* bq = (const float*)d_in[2];
  const float* Wk = (const float*)d_in[3];
  const float* bk = (const float*)d_in[4];
  const float* Wv = (const float*)d_in[5];
  const float* bv = (const float*)d_in[6];
  const float* Wo = (const float*)d_in[7];
  const float* bo = (const float*)d_in[8];
  const float* pb = (const float*)d_in[9];
  float* out = (float*)d_out;

  cudaFuncSetAttribute(k_proj_mma,  cudaFuncAttributeMaxDynamicSharedMemorySize, PRJ_SMEM);
  cudaFuncSetAttribute(k_aft_mma,   cudaFuncAttributeMaxDynamicSharedMemorySize, AFT_SMEM);
  cudaFuncSetAttribute(k_oproj_mma, cudaFuncAttributeMaxDynamicSharedMemorySize, OP_SMEM);

  k_prepw    <<<dim3(4, 8), 128>>>(Wq, Wk, Wv, Wo);
  k_pb       <<<SL, 128>>>(pb);
  k_proj_mma <<<dim3(SL/128, NB), 256, PRJ_SMEM>>>(x, bq, bk, bv);
  k_sum2     <<<NB, 128>>>();
  k_aft_mma  <<<dim3(SL/ATI, NB, 2), 256, AFT_SMEM>>>();
  k_oproj_mma<<<dim3(SL/128, NB), 256, OP_SMEM>>>(bo, out);
}

// round 16
// speedup vs baseline: 6.4509x; 1.2488x over previous
#include <cuda_runtime.h>
#include <cuda_bf16.h>
#include <cstdint>

#define DM   128
#define SL   2048
#define NB   32
#define WIN  64
#define WROW 132
#define NTILE 16                 // 128-l tiles per sequence (proj)

// ---- proj smem (2 CTAs/SM) ----
#define PPITCH 136               // bf16 elems/row; 272B stride -> conflict-free ldmatrix
#define PRJ_AH 0
#define PRJ_AL 34816
#define PRJ_BH 69632             // B chunk [64][136] hi
#define PRJ_BL 87040             // B chunk [64][136] lo
#define PRJ_RED 104448           // redE[4][128], redU[4][128] fp32
#define PRJ_BIAS (PRJ_RED + 4096)
#define PRJ_SMEM (PRJ_BIAS + 1536)    // 110080 -> 2 CTAs/SM

// ---- fused aft+oproj smem (1 CTA/SM) ----
#define ATI  64                  // i-tile
#define AKP  192                 // padded K (window 190)
#define APW  200                 // w-A pitch (400B)
#define AFT_A   0                // [64][200] bf16 = 25600
#define AFT_SS  25600            // Su[128], Se[128] fp32 = 1024
#define AFT_WOH 26624            // Wo hi [128][136] bf16 = 34816
#define AFT_WOL 61440            // Wo lo
#define AFT_BU  96256            // u window [192][136] bf16 = 52224
#define AFT_BE  148480           // e window [192][136] bf16 = 52224
#define AFT_YH  96256            // overlay BU: y hi [64][136] = 17408
#define AFT_YL  113664           // overlay BU: y lo
#define AFT_ST  148480           // overlay BE: stage fp32 [128][68] = 34816
#define AFT_SMEM 200704

// ---------- scratch ----------
__device__ float g_q[(size_t)NB*SL*DM];   // q
__device__ float g_k[(size_t)NB*SL*DM];   // e = exp(k)
__device__ float g_v[(size_t)NB*SL*DM];   // u = e*v
__device__ float g_w[(size_t)SL*WROW];    // exp(pb)-1 padded band rows
__device__ float g_pse[NB*NTILE*DM];
__device__ float g_psu[NB*NTILE*DM];
__device__ float g_Se[NB*DM];
__device__ float g_Su[NB*DM];
__device__ __nv_bfloat16 g_Wimg[4][2][DM*PPITCH];  // [q,k,v,o][hi/lo][c][d]

// ---------- helpers ----------
__device__ __forceinline__ uint32_t smem_u32(const void* p){
  uint32_t a;
  asm("{ .reg .u64 t; cvta.to.shared.u64 t, %1; cvt.u32.u64 %0, t; }" : "=r"(a) : "l"(p));
  return a;
}
__device__ __forceinline__ void ldm4(uint32_t* r, uint32_t a){
  asm volatile("ldmatrix.sync.aligned.m8n8.x4.shared.b16 {%0,%1,%2,%3}, [%4];"
    : "=r"(r[0]),"=r"(r[1]),"=r"(r[2]),"=r"(r[3]) : "r"(a));
}
__device__ __forceinline__ void ldm4t(uint32_t* r, uint32_t a){
  asm volatile("ldmatrix.sync.aligned.m8n8.x4.trans.shared.b16 {%0,%1,%2,%3}, [%4];"
    : "=r"(r[0]),"=r"(r[1]),"=r"(r[2]),"=r"(r[3]) : "r"(a));
}
__device__ __forceinline__ void hmma(float* c, const uint32_t* a, uint32_t b0, uint32_t b1){
  asm volatile("mma.sync.aligned.m16n8k16.row.col.f32.bf16.bf16.f32 "
    "{%0,%1,%2,%3}, {%4,%5,%6,%7}, {%8,%9}, {%0,%1,%2,%3};"
    : "+f"(c[0]),"+f"(c[1]),"+f"(c[2]),"+f"(c[3])
    : "r"(a[0]),"r"(a[1]),"r"(a[2]),"r"(a[3]),"r"(b0),"r"(b1));
}
__device__ __forceinline__ float sigm(float x){
  return __fdividef(1.f, 1.f + __expf(-x));
}

// one 64-K chunk of the 128x128 split GEMM; B chunk local rows [0,64)
__device__ __forceinline__ void gemm_chunk(
    uint32_t AhU, uint32_t AlU, uint32_t BhU, uint32_t BlU,
    int wm, int wn, int lane, int kabs0, float C[2][8][4])
{
  const uint32_t arow = wm*32 + (lane&15);
  const uint32_t kg = (lane>>4)*8;
  const uint32_t brow = lane&15;
  #pragma unroll
  for (int ks=0; ks<4; ks++){
    const uint32_t ka = kabs0 + ks*16;
    const uint32_t kb = ks*16;
    uint32_t ah[2][4], al[2][4];
    #pragma unroll
    for (int mf=0;mf<2;mf++){
      uint32_t off = ((arow + mf*16)*PPITCH + ka + kg)*2;
      ldm4(ah[mf], AhU + off);
      ldm4(al[mf], AlU + off);
    }
    uint32_t bh[8][2], bl[8][2];
    #pragma unroll
    for (int np=0;np<4;np++){
      uint32_t off = ((kb + brow)*PPITCH + wn*64 + np*16 + kg)*2;
      uint32_t t[4];
      ldm4t(t, BhU + off);
      bh[np*2][0]=t[0]; bh[np*2][1]=t[1]; bh[np*2+1][0]=t[2]; bh[np*2+1][1]=t[3];
      ldm4t(t, BlU + off);
      bl[np*2][0]=t[0]; bl[np*2][1]=t[1]; bl[np*2+1][0]=t[2]; bl[np*2+1][1]=t[3];
    }
    #pragma unroll
    for (int mf=0;mf<2;mf++)
      #pragma unroll
      for (int nf=0;nf<8;nf++){
        hmma(C[mf][nf], ah[mf], bh[nf][0], bh[nf][1]);
        hmma(C[mf][nf], ah[mf], bl[nf][0], bl[nf][1]);
        hmma(C[mf][nf], al[mf], bh[nf][0], bh[nf][1]);
      }
  }
}

// ---------------------------------------------------------------------------
// K0: split W's into bf16 hi/lo images, [c][d] pitch 136.
// ---------------------------------------------------------------------------
__global__ void __launch_bounds__(128) k_prepw(
    const float* __restrict__ Wq, const float* __restrict__ Wk,
    const float* __restrict__ Wv, const float* __restrict__ Wo)
{
  const int m = blockIdx.x, cs = blockIdx.y;
  const float* W = (m==0) ? Wq : (m==1) ? Wk : (m==2) ? Wv : Wo;
  const int d = threadIdx.x;
  for (int c = cs*16; c < cs*16 + 16; c++){
    float w = W[(size_t)c*DM + d];
    __nv_bfloat16 h = __float2bfloat16(w);
    __nv_bfloat16 l = __float2bfloat16(w - __bfloat162float(h));
    g_Wimg[m][0][c*PPITCH + d] = h;
    g_Wimg[m][1][c*PPITCH + d] = l;
  }
}

// ---------------------------------------------------------------------------
// K1: tensor-core QKV projection + fused e=exp(k), u=e*v, tile column sums.
// B streamed in two 64-K chunks -> 110 KB smem -> 2 CTAs/SM.
// ---------------------------------------------------------------------------
__global__ void __launch_bounds__(256, 2) k_proj_mma(
    const float* __restrict__ x,  const float* __restrict__ bq,
    const float* __restrict__ bk, const float* __restrict__ bv)
{
  extern __shared__ char smem[];
  const int lt = blockIdx.x, n = blockIdx.y, l0 = lt*128;
  const int tid = threadIdx.x, wid = tid>>5, lane = tid&31;
  const int wm = wid&3, wn = wid>>2;
  __nv_bfloat16* Ah = (__nv_bfloat16*)(smem + PRJ_AH);
  __nv_bfloat16* Al = (__nv_bfloat16*)(smem + PRJ_AL);
  float* redE  = (float*)(smem + PRJ_RED);       // [4][128]
  float* redU  = redE + 512;
  float* sbias = redU + 512;                     // [k|v|q][128]
  const uint32_t AhU = smem_u32(Ah), AlU = smem_u32(Al);
  const uint32_t BhU = smem_u32(smem + PRJ_BH), BlU = smem_u32(smem + PRJ_BL);
  float4* dh_ = (float4*)(smem + PRJ_BH);
  float4* dl_ = (float4*)(smem + PRJ_BL);

  if (tid < 128){
    sbias[tid] = bk[tid]; sbias[128+tid] = bv[tid]; sbias[256+tid] = bq[tid];
  }

  // A = x^T tile: [l][c] hi/lo
  const float* xb = x + ((size_t)n*DM)*SL + l0;
  for (int idx = tid; idx < 128*32; idx += 256){
    int c = idx >> 5, l4 = (idx & 31)*4;
    float4 v4 = *(const float4*)(xb + (size_t)c*SL + l4);
    float vv[4] = {v4.x, v4.y, v4.z, v4.w};
    #pragma unroll
    for (int j=0;j<4;j++){
      __nv_bfloat16 h = __float2bfloat16(vv[j]);
      __nv_bfloat16 l = __float2bfloat16(vv[j] - __bfloat162float(h));
      Ah[(l4+j)*PPITCH + c] = h;
      Al[(l4+j)*PPITCH + c] = l;
    }
  }

  const int erow = l0 + wm*32 + (lane>>2);
  const int ecl0 = wn*64 + (lane&3)*2;
  float C[2][8][4];
  const int morder[3] = {1, 2, 0};   // k, v, q

  for (int pp = 0; pp < 3; pp++){
    const int p = morder[pp];
    #pragma unroll
    for (int mf=0;mf<2;mf++)
      #pragma unroll
      for (int nf=0;nf<8;nf++)
        #pragma unroll
        for (int k=0;k<4;k++) C[mf][nf][k] = 0.f;

    #pragma unroll
    for (int ch = 0; ch < 2; ch++){
      const float4* sh_ = (const float4*)g_Wimg[p][0] + ch*1088;
      const float4* sl_ = (const float4*)g_Wimg[p][1] + ch*1088;
      for (int i = tid; i < 1088; i += 256){ dh_[i] = sh_[i]; dl_[i] = sl_[i]; }
      __syncthreads();
      gemm_chunk(AhU, AlU, BhU, BlU, wm, wn, lane, ch*64, C);
      __syncthreads();
    }

    if (p == 1){  // k -> e = exp(k)
      float sE[8][2];
      #pragma unroll
      for (int nf=0;nf<8;nf++){ sE[nf][0]=0.f; sE[nf][1]=0.f; }
      #pragma unroll
      for (int mf=0;mf<2;mf++)
        #pragma unroll
        for (int nf=0;nf<8;nf++){
          int col = ecl0 + nf*8;
          float b0 = sbias[col], b1 = sbias[col+1];
          float e0 = __expf(C[mf][nf][0]+b0);
          float e1 = __expf(C[mf][nf][1]+b1);
          float e2 = __expf(C[mf][nf][2]+b0);
          float e3 = __expf(C[mf][nf][3]+b1);
          int r = erow + mf*16;
          *(float2*)(g_k + ((size_t)n*SL + r    )*DM + col) = make_float2(e0,e1);
          *(float2*)(g_k + ((size_t)n*SL + r + 8)*DM + col) = make_float2(e2,e3);
          sE[nf][0] += e0+e2; sE[nf][1] += e1+e3;
        }
      #pragma unroll
      for (int nf=0;nf<8;nf++){
        float s0 = sE[nf][0], s1 = sE[nf][1];
        s0 += __shfl_down_sync(0xFFFFFFFFu, s0, 16);
        s0 += __shfl_down_sync(0xFFFFFFFFu, s0, 8);
        s0 += __shfl_down_sync(0xFFFFFFFFu, s0, 4);
        s1 += __shfl_down_sync(0xFFFFFFFFu, s1, 16);
        s1 += __shfl_down_sync(0xFFFFFFFFu, s1, 8);
        s1 += __shfl_down_sync(0xFFFFFFFFu, s1, 4);
        if (lane < 4){
          int col = wn*64 + nf*8 + lane*2;
          redE[wm*128 + col] = s0;
          redE[wm*128 + col + 1] = s1;
        }
      }
    } else if (p == 2){  // v -> u = e*v
      float sU[8][2];
      #pragma unroll
      for (int nf=0;nf<8;nf++){ sU[nf][0]=0.f; sU[nf][1]=0.f; }
      #pragma unroll
      for (int mf=0;mf<2;mf++)
        #pragma unroll
        for (int nf=0;nf<8;nf++){
          int col = ecl0 + nf*8;
          float b0 = sbias[128+col], b1 = sbias[128+col+1];
          int r = erow + mf*16;
          float2 e01 = *(const float2*)(g_k + ((size_t)n*SL + r    )*DM + col);
          float2 e23 = *(const float2*)(g_k + ((size_t)n*SL + r + 8)*DM + col);
          float u0 = e01.x * (C[mf][nf][0]+b0);
          float u1 = e01.y * (C[mf][nf][1]+b1);
          float u2 = e23.x * (C[mf][nf][2]+b0);
          float u3 = e23.y * (C[mf][nf][3]+b1);
          *(float2*)(g_v + ((size_t)n*SL + r    )*DM + col) = make_float2(u0,u1);
          *(float2*)(g_v + ((size_t)n*SL + r + 8)*DM + col) = make_float2(u2,u3);
          sU[nf][0] += u0+u2; sU[nf][1] += u1+u3;
        }
      #pragma unroll
      for (int nf=0;nf<8;nf++){
        float s0 = sU[nf][0], s1 = sU[nf][1];
        s0 += __shfl_down_sync(0xFFFFFFFFu, s0, 16);
        s0 += __shfl_down_sync(0xFFFFFFFFu, s0, 8);
        s0 += __shfl_down_sync(0xFFFFFFFFu, s0, 4);
        s1 += __shfl_down_sync(0xFFFFFFFFu, s1, 16);
        s1 += __shfl_down_sync(0xFFFFFFFFu, s1, 8);
        s1 += __shfl_down_sync(0xFFFFFFFFu, s1, 4);
        if (lane < 4){
          int col = wn*64 + nf*8 + lane*2;
          redU[wm*128 + col] = s0;
          redU[wm*128 + col + 1] = s1;
        }
      }
    } else {             // q
      #pragma unroll
      for (int mf=0;mf<2;mf++)
        #pragma unroll
        for (int nf=0;nf<8;nf++){
          int col = ecl0 + nf*8;
          float b0 = sbias[256+col], b1 = sbias[256+col+1];
          int r = erow + mf*16;
          *(float2*)(g_q + ((size_t)n*SL + r    )*DM + col) = make_float2(C[mf][nf][0]+b0, C[mf][nf][1]+b1);
          *(float2*)(g_q + ((size_t)n*SL + r + 8)*DM + col) = make_float2(C[mf][nf][2]+b0, C[mf][nf][3]+b1);
        }
    }
  }
  __syncthreads();

  if (tid < 128){
    g_pse[((size_t)n*NTILE + lt)*DM + tid] = redE[tid]+redE[128+tid]+redE[256+tid]+redE[384+tid];
    g_psu[((size_t)n*NTILE + lt)*DM + tid] = redU[tid]+redU[128+tid]+redU[256+tid]+redU[384+tid];
  }
}

// ---------------------------------------------------------------------------
// K2: reduce tile partials to Se, Su
// ---------------------------------------------------------------------------
__global__ void __launch_bounds__(128) k_sum2()
{
  const int n = blockIdx.x, d = threadIdx.x;
  float se = 0.f, su = 0.f;
  #pragma unroll
  for (int t = 0; t < NTILE; t++){
    se += g_pse[((size_t)n*NTILE + t)*DM + d];
    su += g_psu[((size_t)n*NTILE + t)*DM + d];
  }
  g_Se[n*DM + d] = se;
  g_Su[n*DM + d] = su;
}

// ---------------------------------------------------------------------------
// K3: band weights (no max): w[i][1+t] = exp(pb[i,j]) - 1 inside band
// ---------------------------------------------------------------------------
__global__ void __launch_bounds__(128) k_pb(const float* __restrict__ pbias)
{
  const int i = blockIdx.x;
  for (int tw = threadIdx.x; tw < WROW; tw += 128){
    float val = 0.f;
    if (tw >= 1 && tw <= 127){
      int j = i - WIN + tw;
      if (j >= 0 && j < SL) val = __expf(pbias[(size_t)i*SL + j]) - 1.f;
    }
    g_w[(size_t)i*WROW + tw] = val;
  }
}

// ---------------------------------------------------------------------------
// K4: FUSED banded AFT + sigmoid gate + output projection + transpose.
// Per (i-tile 64, n):  num = w@u + Su, den = w@e + Se (full d=128),
// y = sigm(q)*num/den kept on-chip -> split bf16 -> y@Wo -> out[n][c][l].
// ---------------------------------------------------------------------------
__global__ void __launch_bounds__(256, 1) k_aftproj(
    const float* __restrict__ bo, float* __restrict__ out)
{
  extern __shared__ char smem[];
  __nv_bfloat16* Aw = (__nv_bfloat16*)(smem + AFT_A);
  float* ss = (float*)(smem + AFT_SS);   // Su[128], Se[128]
  __nv_bfloat16* Bu = (__nv_bfloat16*)(smem + AFT_BU);
  __nv_bfloat16* Be = (__nv_bfloat16*)(smem + AFT_BE);
  __nv_bfloat16* Yh = (__nv_bfloat16*)(smem + AFT_YH);
  __nv_bfloat16* Yl = (__nv_bfloat16*)(smem + AFT_YL);
  float* st = (float*)(smem + AFT_ST);   // [128 d][68 l]
  const uint32_t AwU = smem_u32(Aw);
  const uint32_t BuU = smem_u32(Bu), BeU = smem_u32(Be);
  const uint32_t YhU = smem_u32(Yh), YlU = smem_u32(Yl);
  const uint32_t WohU = smem_u32(smem + AFT_WOH), WolU = smem_u32(smem + AFT_WOL);
  const int it = blockIdx.x, n = blockIdx.y;
  const int i0 = it*ATI, j0 = i0 - (WIN-1);
  const int tid = threadIdx.x, wid = tid>>5, lane = tid&31;
  const int wm = wid&3, wn = wid>>2;

  if (tid < 128){
    ss[tid]     = g_Su[n*DM + tid];
    ss[128+tid] = g_Se[n*DM + tid];
  }
  // Wo images -> smem
  {
    const float4* sh_ = (const float4*)g_Wimg[3][0];
    const float4* sl_ = (const float4*)g_Wimg[3][1];
    float4* dh_ = (float4*)(smem + AFT_WOH);
    float4* dl_ = (float4*)(smem + AFT_WOL);
    for (int i = tid; i < 2176; i += 256){ dh_[i] = sh_[i]; dl_[i] = sl_[i]; }
  }
  // u/e windows [192][136] bf16 (rows 190 valid + pad)
  const float* ug = g_v + ((size_t)n*SL)*DM;
  const float* eg = g_k + ((size_t)n*SL)*DM;
  for (int idx = tid; idx < AKP*32; idx += 256){
    int row = idx>>5, c4 = (idx&31)*4;
    int j = j0 + row;
    float4 fu, fe;
    if (row < (ATI + 2*WIN - 2) && j >= 0 && j < SL){
      fu = *(const float4*)(ug + (size_t)j*DM + c4);
      fe = *(const float4*)(eg + (size_t)j*DM + c4);
    } else { fu = make_float4(0.f,0.f,0.f,0.f); fe = fu; }
    *(__nv_bfloat162*)&Bu[row*PPITCH + c4]     = __floats2bfloat162_rn(fu.x, fu.y);
    *(__nv_bfloat162*)&Bu[row*PPITCH + c4 + 2] = __floats2bfloat162_rn(fu.z, fu.w);
    *(__nv_bfloat162*)&Be[row*PPITCH + c4]     = __floats2bfloat162_rn(fe.x, fe.y);
    *(__nv_bfloat162*)&Be[row*PPITCH + c4 + 2] = __floats2bfloat162_rn(fe.z, fe.w);
  }
  // A fill: Aw[il][jj] = w(i0+il, j0+jj); tw = jj - il + 1 in [1,127]
  for (int idx = tid; idx < ATI*(AKP/4); idx += 256){
    int il = idx / (AKP/4), q4 = (idx % (AKP/4))*4;
    const float* wr = g_w + (size_t)(i0+il)*WROW;
    #pragma unroll
    for (int j=0;j<4;j++){
      int jj = q4 + j;
      int tw = jj - il + 1;
      float w = (tw >= 1 && tw <= 127) ? wr[tw] : 0.f;
      Aw[il*APW + jj] = __float2bfloat16(w);
    }
  }
  __syncthreads();

  // ---- aft GEMMs: Cn = w@u, Cd = w@e  (warp: 16 i-rows x 64 d-cols) ----
  float Cn[8][4], Cd[8][4];
  #pragma unroll
  for (int nf=0;nf<8;nf++)
    #pragma unroll
    for (int k=0;k<4;k++){ Cn[nf][k]=0.f; Cd[nf][k]=0.f; }

  {
    const uint32_t arow = wm*16 + (lane&15);
    const uint32_t kg = (lane>>4)*8;
    const uint32_t brow = lane&15;
    #pragma unroll
    for (int ks=0; ks<AKP/16; ks++){
      const uint32_t k0 = ks*16;
      uint32_t a[4];
      ldm4(a, AwU + (arow*APW + k0 + kg)*2);
      uint32_t bu[8][2], be[8][2];
      #pragma unroll
      for (int np=0;np<4;np++){
        uint32_t off = ((k0 + brow)*PPITCH + wn*64 + np*16 + kg)*2;
        uint32_t t[4];
        ldm4t(t, BuU + off);
        bu[np*2][0]=t[0]; bu[np*2][1]=t[1]; bu[np*2+1][0]=t[2]; bu[np*2+1][1]=t[3];
        ldm4t(t, BeU + off);
        be[np*2][0]=t[0]; be[np*2][1]=t[1]; be[np*2+1][0]=t[2]; be[np*2+1][1]=t[3];
      }
      #pragma unroll
      for (int nf=0;nf<8;nf++){
        hmma(Cn[nf], a, bu[nf][0], bu[nf][1]);
        hmma(Cd[nf], a, be[nf][0], be[nf][1]);
      }
    }
  }

  // ---- y = sigm(q)*(Cn+Su)/(Cd+Se) into registers ----
  const int rowl = wm*16 + (lane>>2);          // local i row (+8 second)
  float yv[8][4];
  #pragma unroll
  for (int nf=0;nf<8;nf++){
    int col = wn*64 + nf*8 + (lane&3)*2;
    float su0 = ss[col], su1 = ss[col+1];
    float se0 = ss[128+col], se1 = ss[128+col+1];
    const float* qp = g_q + ((size_t)n*SL + i0 + rowl)*DM + col;
    float2 q01 = *(const float2*)qp;
    float2 q23 = *(const float2*)(qp + 8*DM);
    yv[nf][0] = sigm(q01.x) * __fdividef(Cn[nf][0]+su0, Cd[nf][0]+se0);
    yv[nf][1] = sigm(q01.y) * __fdividef(Cn[nf][1]+su1, Cd[nf][1]+se1);
    yv[nf][2] = sigm(q23.x) * __fdividef(Cn[nf][2]+su0, Cd[nf][2]+se0);
    yv[nf][3] = sigm(q23.y) * __fdividef(Cn[nf][3]+su1, Cd[nf][3]+se1);
  }
  __syncthreads();   // everyone done reading Bu/Be

  // ---- store y hi/lo into smem (overlay Bu) ----
  #pragma unroll
  for (int nf=0;nf<8;nf++){
    int col = wn*64 + nf*8 + (lane&3)*2;
    __nv_bfloat162 h0 = __floats2bfloat162_rn(yv[nf][0], yv[nf][1]);
    __nv_bfloat162 l0 = __floats2bfloat162_rn(yv[nf][0] - __bfloat162float(h0.x),
                                              yv[nf][1] - __bfloat162float(h0.y));
    __nv_bfloat162 h1 = __floats2bfloat162_rn(yv[nf][2], yv[nf][3]);
    __nv_bfloat162 l1 = __floats2bfloat162_rn(yv[nf][2] - __bfloat162float(h1.x),
                                              yv[nf][3] - __bfloat162float(h1.y));
    *(__nv_bfloat162*)&Yh[rowl*PPITCH + col]       = h0;
    *(__nv_bfloat162*)&Yl[rowl*PPITCH + col]       = l0;
    *(__nv_bfloat162*)&Yh[(rowl+8)*PPITCH + col]   = h1;
    *(__nv_bfloat162*)&Yl[(rowl+8)*PPITCH + col]   = l1;
  }
  __syncthreads();

  // ---- oproj GEMM: C2 = y @ Wo (2-term split), warp 16 rows x 64 cols ----
  float C2[8][4];
  #pragma unroll
  for (int nf=0;nf<8;nf++)
    #pragma unroll
    for (int k=0;k<4;k++) C2[nf][k] = 0.f;
  {
    const uint32_t arow = wm*16 + (lane&15);
    const uint32_t kg = (lane>>4)*8;
    const uint32_t brow = lane&15;
    #pragma unroll
    for (int ks=0; ks<8; ks++){
      const uint32_t k0 = ks*16;
      uint32_t ah[4], al[4];
      ldm4(ah, YhU + (arow*PPITCH + k0 + kg)*2);
      ldm4(al, YlU + (arow*PPITCH + k0 + kg)*2);
      uint32_t wh[8][2], wl[8][2];
      #pragma unroll
      for (int np=0;np<4;np++){
        uint32_t off = ((k0 + brow)*PPITCH + wn*64 + np*16 + kg)*2;
        uint32_t t[4];
        ldm4t(t, WohU + off);
        wh[np*2][0]=t[0]; wh[np*2][1]=t[1]; wh[np*2+1][0]=t[2]; wh[np*2+1][1]=t[3];
        ldm4t(t, WolU + off);
        wl[np*2][0]=t[0]; wl[np*2][1]=t[1]; wl[np*2+1][0]=t[2]; wl[np*2+1][1]=t[3];
      }
      #pragma unroll
      for (int nf=0;nf<8;nf++){
        hmma(C2[nf], ah, wh[nf][0], wh[nf][1]);
        hmma(C2[nf], ah, wl[nf][0], wl[nf][1]);
        hmma(C2[nf], al, wh[nf][0], wh[nf][1]);
      }
    }
  }
  __syncthreads();   // Be region free -> stage

  // ---- stage transpose (+bias) ----
  #pragma unroll
  for (int nf=0;nf<8;nf++){
    int col = wn*64 + nf*8 + (lane&3)*2;
    float b0 = __ldg(bo + col), b1 = __ldg(bo + col + 1);
    st[col*68 + rowl]           = C2[nf][0] + b0;
    st[(col+1)*68 + rowl]       = C2[nf][1] + b1;
    st[col*68 + rowl + 8]       = C2[nf][2] + b0;
    st[(col+1)*68 + rowl + 8]   = C2[nf][3] + b1;
  }
  __syncthreads();

  // ---- coalesced transposed store: out[n][d][i0..i0+63] ----
  for (int idx = tid; idx < 128*16; idx += 256){
    int d = idx >> 4, l4 = (idx & 15)*4;
    float4 v4 = *(const float4*)&st[d*68 + l4];
    *(float4*)(out + ((size_t)n*DM + d)*SL + i0 + l4) = v4;
  }
}

// ---------------------------------------------------------------------------
extern "C" void kernel_launch(void* const* d_in, const int* in_sizes, int n_in,
                              void* d_out, int out_size)
{
  const float* x  = (const float*)d_in[0];
  const float* Wq = (const float*)d_in[1];
  const float* bq = (const float*)d_in[2];
  const float* Wk = (const float*)d_in[3];
  const float* bk = (const float*)d_in[4];
  const float* Wv = (const float*)d_in[5];
  const float* bv = (const float*)d_in[6];
  const float* Wo = (const float*)d_in[7];
  const float* bo = (const float*)d_in[8];
  const float* pb = (const float*)d_in[9];
  float* out = (float*)d_out;

  cudaFuncSetAttribute(k_proj_mma, cudaFuncAttributeMaxDynamicSharedMemorySize, PRJ_SMEM);
  cudaFuncSetAttribute(k_aftproj,  cudaFuncAttributeMaxDynamicSharedMemorySize, AFT_SMEM);

  k_prepw   <<<dim3(4, 8), 128>>>(Wq, Wk, Wv, Wo);
  k_pb      <<<SL, 128>>>(pb);
  k_proj_mma<<<dim3(SL/128, NB), 256, PRJ_SMEM>>>(x, bq, bk, bv);
  k_sum2    <<<NB, 128>>>();
  k_aftproj <<<dim3(SL/ATI, NB), 256, AFT_SMEM>>>(bo, out);
}